// round 13
// baseline (speedup 1.0000x reference)
#include <cuda_runtime.h>
#include <cuda_bf16.h>
#include <cstdint>
#include <math.h>

// ---------------------------------------------------------------------------
// Seq2Seq LSTM (B=64, S=1024, T=512, H=512, D_IN=D_OUT=32), fp32.
// Persistent kernel: 128 CTAs x 512 threads, flag grid barrier (CTA0 agg).
// Each CTA owns 16 gate-rows (4 units x 4 gates) x 64 batches per layer-tile.
// Encoder phases merged (L1(t-1)+L0(t) in one barrier). Decoder unmerged.
// Staging via cp.async.cg into a warp-private 2-slot ring (8-k chunks,
// depth-1 pipeline, exact wait_group discipline).
// Decoder feedback GEMM folded into precomputed gM = dec_Wih0 @ out_W.
// ---------------------------------------------------------------------------

typedef unsigned int u32;

#define NB   128
#define NT   512
#define B_    64
#define H_    512
#define G4   2048
#define DIN   32
#define SLEN 1024
#define TLEN  512

#define BUFSZ (2 * 512)               // 2 ring slots x (64 rows x 8 floats)
#define REDBASE (16 * BUFSZ)          // 16384 floats
#define RROW  1042                    // unmerged reduction row stride
#define RROW2 520                     // merged reduction row stride
#define SMEM_FLOATS (REDBASE + 16 * RROW)    // >= REDBASE + 32*RROW2
#define SMEM_BYTES  (SMEM_FLOATS * 4)        // 132224 B

struct P {
    const float *src;
    const float *eWih0, *eWhh0, *ebih0, *ebhh0;
    const float *eWih1, *eWhh1, *ebih1, *ebhh1;
    const float *dWih0, *dWhh0, *dbih0, *dbhh0;
    const float *dWih1, *dWhh1, *dbih1, *dbhh1;
    const float *outW, *outB;
    float *out;
};

// ---- persistent state (device globals; allocation-free scratch) ----
__device__ float gH0[2][B_ * H_];
__device__ float gH1[2][B_ * H_];
__device__ float gC0[B_ * H_];
__device__ float gC1[B_ * H_];
__device__ float gM[G4 * H_];      // dec_Wih0 @ out_W   [2048 x 512]
__device__ float gB2[G4];          // dec_Wih0 @ out_b
__device__ unsigned gFlag[NB];     // monotonic per-CTA arrival counters
__device__ volatile unsigned g_gen = 0;

// Proven barrier: CTA0's 128 threads poll the per-CTA flags; thread0
// publishes the new generation; other CTAs poll g_gen only.
__device__ __forceinline__ void grid_bar(unsigned &bgen) {
    __threadfence();
    __syncthreads();
    bgen++;
    if (blockIdx.x == 0) {
        if (threadIdx.x > 0 && threadIdx.x < NB) {
            volatile unsigned* f = gFlag + threadIdx.x;
            while (*f < bgen) __nanosleep(32);
        }
        __syncthreads();
        if (threadIdx.x == 0) { __threadfence(); g_gen = bgen; }
    } else {
        if (threadIdx.x == 0) {
            ((volatile unsigned*)gFlag)[blockIdx.x] = bgen;
            while (g_gen < bgen) __nanosleep(32);
        }
        __syncthreads();
    }
}

__device__ __forceinline__ float sigm(float x) { return 1.0f / (1.0f + expf(-x)); }

__device__ __forceinline__ float fma4(float4 a, float4 b, float s) {
    return fmaf(a.x, b.x, fmaf(a.y, b.y, fmaf(a.z, b.z, fmaf(a.w, b.w, s))));
}

// ---- cp.async helpers (L2-only .cg path: coherent with __stcg writes) ----
__device__ __forceinline__ void cpasync16(u32 saddr, const float* gptr) {
    asm volatile("cp.async.cg.shared.global [%0], [%1], 16;"
                 :: "r"(saddr), "l"(gptr) : "memory");
}
__device__ __forceinline__ void cpcommit() {
    asm volatile("cp.async.commit_group;" ::: "memory");
}
__device__ __forceinline__ void cpwait1() {
    asm volatile("cp.async.wait_group 1;" ::: "memory");
}
__device__ __forceinline__ void cpwait0() {
    asm volatile("cp.async.wait_group 0;" ::: "memory");
}

// K=512 GEMM term over a K-slice: nch chunks of 8 k starting at kbase.
// acc[4 rows][8 batches]. W pre-offset to row 0, row stride WS (template).
// x: [64 rows, stride ld]. 2-slot smem ring (2048 B/slot), depth-1 pipeline.
// Discipline: preamble commits chunk 0. Iter c commits chunk c+1 (if any)
// then wait_group 1; in-order completion guarantees chunk c has landed.
// Last iter uses wait_group 0.
template<int WS>
__device__ __forceinline__ void termK(
    const float* x, int ld, const float* __restrict__ W,
    int kbase, int nch, int lane, int bq, float acc[4][8],
    const float* buf, u32 bufa)
{
    const float* xr0 = x + (size_t)lane * ld + kbase;
    const float* xr1 = x + (size_t)(lane + 32) * ld + kbase;
    const u32 a0 = bufa + lane * 32;           // row `lane`, 8 floats
    const u32 a1 = bufa + (lane + 32) * 32;    // row `lane+32`

    // preamble: chunk 0 into slot 0
    cpasync16(a0,      xr0);
    cpasync16(a0 + 16, xr0 + 4);
    cpasync16(a1,      xr1);
    cpasync16(a1 + 16, xr1 + 4);
    cpcommit();

    for (int c = 0; c < nch; c++) {
        if (c + 1 < nch) {
            const u32 s = (u32)(((c + 1) & 1) * 2048);
            const float* x0 = xr0 + (c + 1) * 8;
            const float* x1 = xr1 + (c + 1) * 8;
            cpasync16(a0 + s,      x0);
            cpasync16(a0 + s + 16, x0 + 4);
            cpasync16(a1 + s,      x1);
            cpasync16(a1 + s + 16, x1 + 4);
            cpcommit();
            cpwait1();
        } else {
            cpwait0();
        }
        __syncwarp();                    // all lanes' chunk-c data visible
        const float* hb = buf + (c & 1) * 512 + bq * 8;
        const float* wb = W + kbase + c * 8;
        #pragma unroll
        for (int h = 0; h < 2; h++) {
            float4 w0 = __ldg((const float4*)(wb + 0 * WS + h * 4));
            float4 w1 = __ldg((const float4*)(wb + 1 * WS + h * 4));
            float4 w2 = __ldg((const float4*)(wb + 2 * WS + h * 4));
            float4 w3 = __ldg((const float4*)(wb + 3 * WS + h * 4));
            #pragma unroll
            for (int m = 0; m < 8; m++) {
                float4 hv = *(const float4*)(hb + m * 64 + h * 4); // row m*8+bq
                acc[0][m] = fma4(w0, hv, acc[0][m]);
                acc[1][m] = fma4(w1, hv, acc[1][m]);
                acc[2][m] = fma4(w2, hv, acc[2][m]);
                acc[3][m] = fma4(w3, hv, acc[3][m]);
            }
        }
        __syncwarp();                    // slot c&1 free before reuse at c+2
    }
}

// K=32 single 4-k chunk (rows staged at stride 4 floats).
// Wrow0 row stride = DIN.
__device__ __forceinline__ void term32chunk(
    const float* x, int ld, const float* __restrict__ Wrow0,
    int kbase, int lane, int bq, float acc[4][8],
    const float* buf, u32 bufa)
{
    cpasync16(bufa + lane * 16,        x + (size_t)lane * ld + kbase);
    cpasync16(bufa + (lane + 32) * 16, x + (size_t)(lane + 32) * ld + kbase);
    cpcommit();
    cpwait0();
    __syncwarp();
    float4 w0 = __ldg((const float4*)(Wrow0 + 0 * DIN + kbase));
    float4 w1 = __ldg((const float4*)(Wrow0 + 1 * DIN + kbase));
    float4 w2 = __ldg((const float4*)(Wrow0 + 2 * DIN + kbase));
    float4 w3 = __ldg((const float4*)(Wrow0 + 3 * DIN + kbase));
    #pragma unroll
    for (int m = 0; m < 8; m++) {
        float4 hv = *(const float4*)(buf + ((m << 3) + bq) * 4);
        acc[0][m] = fma4(w0, hv, acc[0][m]);
        acc[1][m] = fma4(w1, hv, acc[1][m]);
        acc[2][m] = fma4(w2, hv, acc[2][m]);
        acc[3][m] = fma4(w3, hv, acc[3][m]);
    }
    __syncwarp();
}

// ---- unmerged LSTM phase (decoder + encoder prologue/epilogue) ----
// 16 warps, 32-k slice each per term (4 chunks). KA in {0, 32, 512}.
__device__ __forceinline__ void lstm_phase(
    const float* xA, int ldA, const float* __restrict__ WA, int KA,
    const float* xB, const float* __restrict__ WB,
    const float* __restrict__ bih, const float* __restrict__ bhh,
    const float* __restrict__ b2,
    float* __restrict__ cst, float* __restrict__ hout,
    float* smem, u32 smema)
{
    const int tid  = threadIdx.x;
    const int w    = tid >> 5, lane = tid & 31;
    const int gate = lane >> 3, bq = lane & 7;
    float* buf = smem + w * BUFSZ;
    const u32 bufa = smema + (u32)(w * BUFSZ * 4);
    float* red = smem + REDBASE;

    float acc[4][8];
    #pragma unroll
    for (int r = 0; r < 4; r++)
        #pragma unroll
        for (int m = 0; m < 8; m++) acc[r][m] = 0.0f;

    const size_t rowbase = (size_t)((gate << 9) + (blockIdx.x << 2));
    if (KA == 512)
        termK<512>(xA, ldA, WA + rowbase * H_, w * 32, 4, lane, bq, acc, buf, bufa);
    else if (KA == 32 && w < 8)
        term32chunk(xA, ldA, WA + rowbase * DIN, w * 4, lane, bq, acc, buf, bufa);
    termK<512>(xB, H_, WB + rowbase * H_, w * 32, 4, lane, bq, acc, buf, bufa);

    #pragma unroll
    for (int rr = 0; rr < 4; rr++)
        #pragma unroll
        for (int m = 0; m < 8; m++)
            red[((gate << 2) + rr) * RROW + (w << 6) + (m << 3) + bq] = acc[rr][m];
    __syncthreads();

    if (tid < 256) {
        const int u = tid & 3, b = tid >> 2;
        const int ug = (blockIdx.x << 2) + u;
        float g4v[4];
        #pragma unroll
        for (int g = 0; g < 4; g++) {
            float s = 0.0f;
            #pragma unroll
            for (int s16 = 0; s16 < 16; s16++)
                s += red[((g << 2) + u) * RROW + (s16 << 6) + b];
            int r = (g << 9) + ug;
            s += __ldg(bih + r) + __ldg(bhh + r);
            if (b2) s += __ldg(b2 + r);
            g4v[g] = s;
        }
        const int idx = (b << 9) + ug;
        float cp = __ldcg(cst + idx);
        float cn = sigm(g4v[1]) * cp + sigm(g4v[0]) * tanhf(g4v[2]);
        __stcg(cst + idx, cn);
        __stcg(hout + idx, sigm(g4v[3]) * tanhf(cn));
    }
}

// ---- merged encoder phase t (1..1023): computes L1(t-1) AND L0(t) ----
// Warps 0-7: L0 tile (src(t)@eWih0 + h0(t-1)@eWhh0), 64-k slices (8 chunks).
// Warps 8-15: L1 tile (h0(t-1)@eWih1 + h1(t-2)@eWhh1), 64-k slices.
__device__ __forceinline__ void enc_merged(const P& p, int t,
                                           float* smem, u32 smema)
{
    const int tid  = threadIdx.x;
    const int w    = tid >> 5, lane = tid & 31;
    const int grp  = w >> 3, seg = w & 7;
    const int gate = lane >> 3, bq = lane & 7;
    float* buf = smem + w * BUFSZ;
    const u32 bufa = smema + (u32)(w * BUFSZ * 4);
    float* red = smem + REDBASE;

    float acc[4][8];
    #pragma unroll
    for (int r = 0; r < 4; r++)
        #pragma unroll
        for (int m = 0; m < 8; m++) acc[r][m] = 0.0f;

    const size_t rowbase = (size_t)((gate << 9) + (blockIdx.x << 2));
    const float* h0prev = gH0[(t - 1) & 1];     // h0(t-1)
    if (grp == 0) {
        term32chunk(p.src + t * DIN, SLEN * DIN, p.eWih0 + rowbase * DIN,
                    seg * 4, lane, bq, acc, buf, bufa);
        termK<512>(h0prev, H_, p.eWhh0 + rowbase * H_,
                   seg * 64, 8, lane, bq, acc, buf, bufa);
    } else {
        const float* h1prev2 = gH1[t & 1];      // h1(t-2) lives in buf t&1
        termK<512>(h0prev,  H_, p.eWih1 + rowbase * H_,
                   seg * 64, 8, lane, bq, acc, buf, bufa);
        termK<512>(h1prev2, H_, p.eWhh1 + rowbase * H_,
                   seg * 64, 8, lane, bq, acc, buf, bufa);
    }

    #pragma unroll
    for (int rr = 0; rr < 4; rr++)
        #pragma unroll
        for (int m = 0; m < 8; m++)
            red[((grp << 4) + (gate << 2) + rr) * RROW2 + (seg << 6) + (m << 3) + bq] = acc[rr][m];
    __syncthreads();

    // finalize: 512 threads, one (layer, b, u) each
    {
        const int L = tid >> 8, rem = tid & 255;
        const int u = rem & 3, b = rem >> 2;
        const int ug = (blockIdx.x << 2) + u;
        const float* bih = L ? p.ebih1 : p.ebih0;
        const float* bhh = L ? p.ebhh1 : p.ebhh0;
        float g4v[4];
        #pragma unroll
        for (int g = 0; g < 4; g++) {
            float s = 0.0f;
            #pragma unroll
            for (int s8 = 0; s8 < 8; s8++)
                s += red[((L << 4) + (g << 2) + u) * RROW2 + (s8 << 6) + b];
            int r = (g << 9) + ug;
            s += __ldg(bih + r) + __ldg(bhh + r);
            g4v[g] = s;
        }
        float* cst  = L ? gC1 : gC0;
        float* hout = L ? gH1[(t - 1) & 1] : gH0[t & 1];
        const int idx = (b << 9) + ug;
        float cp = __ldcg(cst + idx);
        float cn = sigm(g4v[1]) * cp + sigm(g4v[0]) * tanhf(g4v[2]);
        __stcg(cst + idx, cn);
        __stcg(hout + idx, sigm(g4v[3]) * tanhf(cn));
    }
}

// pred(t) = h1 @ out_W.T + out_b -> d_out[:, t, :].
// Spread over ALL CTAs: 64 threads/CTA, 16 outputs/CTA.
__device__ __forceinline__ void do_pred(const P& p, const float* __restrict__ h1, int t)
{
    if (threadIdx.x >= 64) return;
    int g = (blockIdx.x << 6) + threadIdx.x;   // 0..8191
    int oid = g >> 2, part = g & 3;            // 2048 outputs, K split by 4
    int b = oid >> 5, j = oid & 31;
    const float* hr = h1 + (b << 9) + (part << 7);
    const float* wr = p.outW + (j << 9) + (part << 7);
    float s = 0.0f;
    #pragma unroll
    for (int k = 0; k < 128; k += 4) {
        float4 hv = __ldcg((const float4*)(hr + k));
        float4 wv = __ldg ((const float4*)(wr + k));
        s = fmaf(hv.x, wv.x, fmaf(hv.y, wv.y, fmaf(hv.z, wv.z, fmaf(hv.w, wv.w, s))));
    }
    s += __shfl_xor_sync(0xffffffffu, s, 1);
    s += __shfl_xor_sync(0xffffffffu, s, 2);
    if (part == 0)
        p.out[((long)b << 14) + (t << 5) + j] = s + __ldg(p.outB + j);
}

__global__ void __launch_bounds__(NT, 1) seq2seq_kernel(P p)
{
    extern __shared__ float smem[];
    const u32 smema = (u32)__cvta_generic_to_shared(smem);
    const int gt = blockIdx.x * NT + threadIdx.x;   // 0..65535
    unsigned bgen = g_gen;                          // monotonic barrier epoch

    // ---- zero init: h(-1) lives in buffer 1 ----
    if (gt < B_ * H_) {
        __stcg(&gH0[1][gt], 0.0f);
        __stcg(&gH1[1][gt], 0.0f);
        __stcg(&gC0[gt],    0.0f);
        __stcg(&gC1[gt],    0.0f);
    }
    grid_bar(bgen);

    // ---- precompute M = dec_Wih0 @ out_W, b2 = dec_Wih0 @ out_b ----
    for (int o = gt; o < G4 * H_; o += NB * NT) {
        int rr = o >> 9, hc = o & 511;
        const float* wr = p.dWih0 + rr * DIN;
        const float* oc = p.outW + hc;
        float s = 0.0f;
        #pragma unroll
        for (int j = 0; j < DIN; j++) s = fmaf(__ldg(wr + j), __ldg(oc + j * H_), s);
        __stcg(&gM[o], s);
    }
    if (gt < G4) {
        const float* wr = p.dWih0 + gt * DIN;
        float s = 0.0f;
        #pragma unroll
        for (int j = 0; j < DIN; j++) s = fmaf(__ldg(wr + j), __ldg(p.outB + j), s);
        __stcg(&gB2[gt], s);
    }
    grid_bar(bgen);

    // ---- encoder ----
    // prologue: L0(0)   (reads h0(-1)=zeros in buf 1, writes h0(0) -> buf 0)
    lstm_phase(p.src, SLEN * DIN, p.eWih0, DIN,
               gH0[1], p.eWhh0,
               p.ebih0, p.ebhh0, nullptr, gC0, gH0[0], smem, smema);
    grid_bar(bgen);
    // merged main loop: phase t computes L1(t-1) and L0(t)
    for (int t = 1; t < SLEN; t++) {
        enc_merged(p, t, smem, smema);
        grid_bar(bgen);
    }
    // epilogue: L1(1023)  (h0(1023) in buf 1, h1(1022) in buf 0 -> h1(1023) buf 1)
    lstm_phase(gH0[1], H_, p.eWih1, H_,
               gH1[0], p.eWhh1,
               p.ebih1, p.ebhh1, nullptr, gC1, gH1[1], smem, smema);
    grid_bar(bgen);

    // ---- decoder: 512 steps x 2 phases (+ pred side job, all CTAs) ----
    // h_dec(t) in buf t&1; h_dec(-1) = encoder finals in buf 1.
    for (int t = 0; t < TLEN; t++) {
        const int rp = (t - 1) & 1, wp = t & 1;
        lstm_phase(t ? gH1[rp] : nullptr, H_, gM, t ? 512 : 0,
                   gH0[rp], p.dWhh0,
                   p.dbih0, p.dbhh0, t ? gB2 : nullptr, gC0, gH0[wp], smem, smema);
        if (t > 0) do_pred(p, gH1[rp], t - 1);
        grid_bar(bgen);
        lstm_phase(gH0[wp], H_, p.dWih1, H_,
                   gH1[rp], p.dWhh1,
                   p.dbih1, p.dbhh1, nullptr, gC1, gH1[wp], smem, smema);
        grid_bar(bgen);
    }
    // final pred for t = TLEN-1 (h1(511) in buf 1)
    do_pred(p, gH1[1], TLEN - 1);
}

extern "C" void kernel_launch(void* const* d_in, const int* in_sizes, int n_in,
                              void* d_out, int out_size)
{
    const int o = (in_sizes[1] < 100) ? 1 : 0;   // skip target_length scalar if present

    P p;
    p.src   = (const float*)d_in[0];
    p.eWih0 = (const float*)d_in[1 + o];
    p.eWhh0 = (const float*)d_in[2 + o];
    p.ebih0 = (const float*)d_in[3 + o];
    p.ebhh0 = (const float*)d_in[4 + o];
    p.eWih1 = (const float*)d_in[5 + o];
    p.eWhh1 = (const float*)d_in[6 + o];
    p.ebih1 = (const float*)d_in[7 + o];
    p.ebhh1 = (const float*)d_in[8 + o];
    p.dWih0 = (const float*)d_in[9 + o];
    p.dWhh0 = (const float*)d_in[10 + o];
    p.dbih0 = (const float*)d_in[11 + o];
    p.dbhh0 = (const float*)d_in[12 + o];
    p.dWih1 = (const float*)d_in[13 + o];
    p.dWhh1 = (const float*)d_in[14 + o];
    p.dbih1 = (const float*)d_in[15 + o];
    p.dbhh1 = (const float*)d_in[16 + o];
    p.outW  = (const float*)d_in[17 + o];
    p.outB  = (const float*)d_in[18 + o];
    p.out   = (float*)d_out;

    cudaFuncSetAttribute(seq2seq_kernel,
                         cudaFuncAttributeMaxDynamicSharedMemorySize, SMEM_BYTES);
    seq2seq_kernel<<<NB, NT, SMEM_BYTES>>>(p);
}

// round 14
// speedup vs baseline: 1.1039x; 1.1039x over previous
#include <cuda_runtime.h>
#include <cuda_bf16.h>
#include <cstdint>
#include <math.h>

// ---------------------------------------------------------------------------
// Seq2Seq LSTM (B=64, S=1024, T=512, H=512, D_IN=D_OUT=32), fp32.
// Persistent kernel: 128 CTAs x 512 threads, flag grid barrier (CTA0 agg).
// Each CTA owns 16 gate-rows (4 units x 4 gates) x 64 batches per layer-tile.
// Encoder phases merged (L1(t-1)+L0(t) in one barrier). Decoder unmerged.
// Staging via cp.async.cg, 3-slot warp-private ring (4-k chunks, depth-2).
// SMEM slimmed to 66 KB: staging ring and reduction tile share one
// per-warp 1056-float region -> ~160 KB L1 left, weights L1-resident.
// Decoder feedback GEMM folded into precomputed gM = dec_Wih0 @ out_W.
// ---------------------------------------------------------------------------

typedef unsigned int u32;

#define NB   128
#define NT   512
#define B_    64
#define H_    512
#define G4   2048
#define DIN   32
#define SLEN 1024
#define TLEN  512
#define CHUNK  4                      // k per staged chunk

#define WREG 1056                     // floats per warp region (16 rows x 66)
#define SMEM_FLOATS (16 * WREG)       // 16896 floats
#define SMEM_BYTES  (SMEM_FLOATS * 4) // 67584 B

struct P {
    const float *src;
    const float *eWih0, *eWhh0, *ebih0, *ebhh0;
    const float *eWih1, *eWhh1, *ebih1, *ebhh1;
    const float *dWih0, *dWhh0, *dbih0, *dbhh0;
    const float *dWih1, *dWhh1, *dbih1, *dbhh1;
    const float *outW, *outB;
    float *out;
};

// ---- persistent state (device globals; allocation-free scratch) ----
__device__ float gH0[2][B_ * H_];
__device__ float gH1[2][B_ * H_];
__device__ float gC0[B_ * H_];
__device__ float gC1[B_ * H_];
__device__ float gM[G4 * H_];      // dec_Wih0 @ out_W   [2048 x 512]
__device__ float gB2[G4];          // dec_Wih0 @ out_b
__device__ unsigned gFlag[NB];     // monotonic per-CTA arrival counters
__device__ volatile unsigned g_gen = 0;

// Proven barrier: CTA0's 128 threads poll the per-CTA flags; thread0
// publishes the new generation; other CTAs poll g_gen only.
__device__ __forceinline__ void grid_bar(unsigned &bgen) {
    __threadfence();
    __syncthreads();
    bgen++;
    if (blockIdx.x == 0) {
        if (threadIdx.x > 0 && threadIdx.x < NB) {
            volatile unsigned* f = gFlag + threadIdx.x;
            while (*f < bgen) __nanosleep(32);
        }
        __syncthreads();
        if (threadIdx.x == 0) { __threadfence(); g_gen = bgen; }
    } else {
        if (threadIdx.x == 0) {
            ((volatile unsigned*)gFlag)[blockIdx.x] = bgen;
            while (g_gen < bgen) __nanosleep(32);
        }
        __syncthreads();
    }
}

__device__ __forceinline__ float sigm(float x) { return 1.0f / (1.0f + expf(-x)); }

__device__ __forceinline__ float fma4(float4 a, float4 b, float s) {
    return fmaf(a.x, b.x, fmaf(a.y, b.y, fmaf(a.z, b.z, fmaf(a.w, b.w, s))));
}

// ---- cp.async helpers (L2-only .cg path: coherent with __stcg writes) ----
__device__ __forceinline__ void cpasync16(u32 saddr, const float* gptr) {
    asm volatile("cp.async.cg.shared.global [%0], [%1], 16;"
                 :: "r"(saddr), "l"(gptr) : "memory");
}
__device__ __forceinline__ void cpcommit() {
    asm volatile("cp.async.commit_group;" ::: "memory");
}
__device__ __forceinline__ void cpwait2() {
    asm volatile("cp.async.wait_group 2;" ::: "memory");
}

// GEMM term over a K-slice: nch chunks of 4 k starting at kbase.
// acc[4 rows][8 batches]. W pre-offset to row 0, row stride WS (template).
// x: [64 rows, stride ld]. 3-slot smem ring (1024 B/slot), depth-2 pipeline.
// Group discipline: preamble commits exactly 2 groups; each iteration
// commits exactly 1 (possibly empty) -> wait_group 2 at iter c guarantees
// chunk c's data has landed for every lane (followed by a syncwarp).
template<int WS>
__device__ __forceinline__ void termK(
    const float* x, int ld, const float* __restrict__ W,
    int kbase, int nch, int lane, int bq, float acc[4][8],
    const float* buf, u32 bufa)
{
    const float* xr0 = x + (size_t)lane * ld + kbase;
    const float* xr1 = x + (size_t)(lane + 32) * ld + kbase;
    const u32 a0 = bufa + lane * 16;
    const u32 a1 = bufa + (lane + 32) * 16;

    // preamble: issue up to 2 chunks, pad to exactly 2 committed groups
    const int pre = (nch < 2) ? nch : 2;
    for (int c = 0; c < pre; c++) {
        const u32 s = (u32)((c % 3) * 1024);
        cpasync16(a0 + s, xr0 + c * CHUNK);
        cpasync16(a1 + s, xr1 + c * CHUNK);
        cpcommit();
    }
    for (int c = pre; c < 2; c++) cpcommit();

    for (int c = 0; c < nch; c++) {
        if (c + 2 < nch) {
            const u32 s = (u32)(((c + 2) % 3) * 1024);
            cpasync16(a0 + s, xr0 + (c + 2) * CHUNK);
            cpasync16(a1 + s, xr1 + (c + 2) * CHUNK);
        }
        cpcommit();
        cpwait2();
        __syncwarp();                    // all lanes' chunk-c data visible
        const float* hb = buf + (c % 3) * 256 + bq * 4;
        const float* wb = W + kbase + c * CHUNK;
        float4 w0 = __ldg((const float4*)(wb + 0 * WS));
        float4 w1 = __ldg((const float4*)(wb + 1 * WS));
        float4 w2 = __ldg((const float4*)(wb + 2 * WS));
        float4 w3 = __ldg((const float4*)(wb + 3 * WS));
        #pragma unroll
        for (int m = 0; m < 8; m++) {
            float4 hv = *(const float4*)(hb + m * 32);   // rows m*8+bq, stride 4
            acc[0][m] = fma4(w0, hv, acc[0][m]);
            acc[1][m] = fma4(w1, hv, acc[1][m]);
            acc[2][m] = fma4(w2, hv, acc[2][m]);
            acc[3][m] = fma4(w3, hv, acc[3][m]);
        }
        __syncwarp();                    // slot c%3 free before c+3 issues
    }
}

// K=32 single 4-k chunk (rows staged at stride 4 floats).
// Wrow0 row stride = DIN. Uses slot 0; issues 1 real + 2 pad commits, then
// drains fully (wait 2 on 3 groups -> oldest (the real one) done; extra
// syncwarp after keeps the discipline identical to termK's exit state).
__device__ __forceinline__ void term32chunk(
    const float* x, int ld, const float* __restrict__ Wrow0,
    int kbase, int lane, int bq, float acc[4][8],
    const float* buf, u32 bufa)
{
    cpasync16(bufa + lane * 16,        x + (size_t)lane * ld + kbase);
    cpasync16(bufa + (lane + 32) * 16, x + (size_t)(lane + 32) * ld + kbase);
    cpcommit();
    cpcommit();
    cpcommit();
    cpwait2();
    __syncwarp();
    float4 w0 = __ldg((const float4*)(Wrow0 + 0 * DIN + kbase));
    float4 w1 = __ldg((const float4*)(Wrow0 + 1 * DIN + kbase));
    float4 w2 = __ldg((const float4*)(Wrow0 + 2 * DIN + kbase));
    float4 w3 = __ldg((const float4*)(Wrow0 + 3 * DIN + kbase));
    #pragma unroll
    for (int m = 0; m < 8; m++) {
        float4 hv = *(const float4*)(buf + ((m << 3) + bq) * 4);
        acc[0][m] = fma4(w0, hv, acc[0][m]);
        acc[1][m] = fma4(w1, hv, acc[1][m]);
        acc[2][m] = fma4(w2, hv, acc[2][m]);
        acc[3][m] = fma4(w3, hv, acc[3][m]);
    }
    __syncwarp();
}

// ---- unmerged LSTM phase (decoder + encoder prologue/epilogue) ----
// 16 warps, 32-k slice each per term (8 chunks). KA in {0, 32, 512}.
__device__ __forceinline__ void lstm_phase(
    const float* xA, int ldA, const float* __restrict__ WA, int KA,
    const float* xB, const float* __restrict__ WB,
    const float* __restrict__ bih, const float* __restrict__ bhh,
    const float* __restrict__ b2,
    float* __restrict__ cst, float* __restrict__ hout,
    float* smem, u32 smema)
{
    const int tid  = threadIdx.x;
    const int w    = tid >> 5, lane = tid & 31;
    const int gate = lane >> 3, bq = lane & 7;
    float* buf = smem + w * WREG;
    const u32 bufa = smema + (u32)(w * WREG * 4);

    float acc[4][8];
    #pragma unroll
    for (int r = 0; r < 4; r++)
        #pragma unroll
        for (int m = 0; m < 8; m++) acc[r][m] = 0.0f;

    const size_t rowbase = (size_t)((gate << 9) + (blockIdx.x << 2));
    if (KA == 512)
        termK<512>(xA, ldA, WA + rowbase * H_, w * 32, 8, lane, bq, acc, buf, bufa);
    else if (KA == 32 && w < 8)
        term32chunk(xA, ldA, WA + rowbase * DIN, w * 4, lane, bq, acc, buf, bufa);
    termK<512>(xB, H_, WB + rowbase * H_, w * 32, 8, lane, bq, acc, buf, bufa);

    // partial store into the warp's OWN region (overwrites its staging):
    // offset = row*66 + b  (bank = gate*8 + bq -> conflict-free)
    #pragma unroll
    for (int rr = 0; rr < 4; rr++)
        #pragma unroll
        for (int m = 0; m < 8; m++)
            buf[((gate << 2) + rr) * 66 + (m << 3) + bq] = acc[rr][m];
    __syncthreads();

    if (tid < 256) {
        const int u = tid & 3, b = tid >> 2;
        const int ug = (blockIdx.x << 2) + u;
        float g4v[4];
        #pragma unroll
        for (int g = 0; g < 4; g++) {
            float s = 0.0f;
            #pragma unroll
            for (int s16 = 0; s16 < 16; s16++)
                s += smem[s16 * WREG + ((g << 2) + u) * 66 + b];
            int r = (g << 9) + ug;
            s += __ldg(bih + r) + __ldg(bhh + r);
            if (b2) s += __ldg(b2 + r);
            g4v[g] = s;
        }
        const int idx = (b << 9) + ug;
        float cp = __ldcg(cst + idx);
        float cn = sigm(g4v[1]) * cp + sigm(g4v[0]) * tanhf(g4v[2]);
        __stcg(cst + idx, cn);
        __stcg(hout + idx, sigm(g4v[3]) * tanhf(cn));
    }
}

// ---- merged encoder phase t (1..1023): computes L1(t-1) AND L0(t) ----
// Warps 0-7: L0 tile (src(t)@eWih0 + h0(t-1)@eWhh0), 64-k slices (16 chunks).
// Warps 8-15: L1 tile (h0(t-1)@eWih1 + h1(t-2)@eWhh1), 64-k slices.
__device__ __forceinline__ void enc_merged(const P& p, int t,
                                           float* smem, u32 smema)
{
    const int tid  = threadIdx.x;
    const int w    = tid >> 5, lane = tid & 31;
    const int grp  = w >> 3, seg = w & 7;
    const int gate = lane >> 3, bq = lane & 7;
    float* buf = smem + w * WREG;
    const u32 bufa = smema + (u32)(w * WREG * 4);

    float acc[4][8];
    #pragma unroll
    for (int r = 0; r < 4; r++)
        #pragma unroll
        for (int m = 0; m < 8; m++) acc[r][m] = 0.0f;

    const size_t rowbase = (size_t)((gate << 9) + (blockIdx.x << 2));
    const float* h0prev = gH0[(t - 1) & 1];     // h0(t-1)
    if (grp == 0) {
        term32chunk(p.src + t * DIN, SLEN * DIN, p.eWih0 + rowbase * DIN,
                    seg * 4, lane, bq, acc, buf, bufa);
        termK<512>(h0prev, H_, p.eWhh0 + rowbase * H_,
                   seg * 64, 16, lane, bq, acc, buf, bufa);
    } else {
        const float* h1prev2 = gH1[t & 1];      // h1(t-2) lives in buf t&1
        termK<512>(h0prev,  H_, p.eWih1 + rowbase * H_,
                   seg * 64, 16, lane, bq, acc, buf, bufa);
        termK<512>(h1prev2, H_, p.eWhh1 + rowbase * H_,
                   seg * 64, 16, lane, bq, acc, buf, bufa);
    }

    // partial store into the warp's OWN region (row within its layer tile)
    #pragma unroll
    for (int rr = 0; rr < 4; rr++)
        #pragma unroll
        for (int m = 0; m < 8; m++)
            buf[((gate << 2) + rr) * 66 + (m << 3) + bq] = acc[rr][m];
    __syncthreads();

    // finalize: 512 threads, one (layer, b, u) each; sum the 8 warps of
    // the thread's layer group.
    {
        const int L = tid >> 8, rem = tid & 255;
        const int u = rem & 3, b = rem >> 2;
        const int ug = (blockIdx.x << 2) + u;
        const float* bih = L ? p.ebih1 : p.ebih0;
        const float* bhh = L ? p.ebhh1 : p.ebhh0;
        float g4v[4];
        #pragma unroll
        for (int g = 0; g < 4; g++) {
            float s = 0.0f;
            #pragma unroll
            for (int s8 = 0; s8 < 8; s8++)
                s += smem[((L << 3) + s8) * WREG + ((g << 2) + u) * 66 + b];
            int r = (g << 9) + ug;
            s += __ldg(bih + r) + __ldg(bhh + r);
            g4v[g] = s;
        }
        float* cst  = L ? gC1 : gC0;
        float* hout = L ? gH1[(t - 1) & 1] : gH0[t & 1];
        const int idx = (b << 9) + ug;
        float cp = __ldcg(cst + idx);
        float cn = sigm(g4v[1]) * cp + sigm(g4v[0]) * tanhf(g4v[2]);
        __stcg(cst + idx, cn);
        __stcg(hout + idx, sigm(g4v[3]) * tanhf(cn));
    }
}

// pred(t) = h1 @ out_W.T + out_b -> d_out[:, t, :].
// Spread over ALL CTAs: 64 threads/CTA, 16 outputs/CTA.
__device__ __forceinline__ void do_pred(const P& p, const float* __restrict__ h1, int t)
{
    if (threadIdx.x >= 64) return;
    int g = (blockIdx.x << 6) + threadIdx.x;   // 0..8191
    int oid = g >> 2, part = g & 3;            // 2048 outputs, K split by 4
    int b = oid >> 5, j = oid & 31;
    const float* hr = h1 + (b << 9) + (part << 7);
    const float* wr = p.outW + (j << 9) + (part << 7);
    float s = 0.0f;
    #pragma unroll
    for (int k = 0; k < 128; k += 4) {
        float4 hv = __ldcg((const float4*)(hr + k));
        float4 wv = __ldg ((const float4*)(wr + k));
        s = fmaf(hv.x, wv.x, fmaf(hv.y, wv.y, fmaf(hv.z, wv.z, fmaf(hv.w, wv.w, s))));
    }
    s += __shfl_xor_sync(0xffffffffu, s, 1);
    s += __shfl_xor_sync(0xffffffffu, s, 2);
    if (part == 0)
        p.out[((long)b << 14) + (t << 5) + j] = s + __ldg(p.outB + j);
}

__global__ void __launch_bounds__(NT, 1) seq2seq_kernel(P p)
{
    extern __shared__ float smem[];
    const u32 smema = (u32)__cvta_generic_to_shared(smem);
    const int gt = blockIdx.x * NT + threadIdx.x;   // 0..65535
    unsigned bgen = g_gen;                          // monotonic barrier epoch

    // ---- zero init: h(-1) lives in buffer 1 ----
    if (gt < B_ * H_) {
        __stcg(&gH0[1][gt], 0.0f);
        __stcg(&gH1[1][gt], 0.0f);
        __stcg(&gC0[gt],    0.0f);
        __stcg(&gC1[gt],    0.0f);
    }
    grid_bar(bgen);

    // ---- precompute M = dec_Wih0 @ out_W, b2 = dec_Wih0 @ out_b ----
    for (int o = gt; o < G4 * H_; o += NB * NT) {
        int rr = o >> 9, hc = o & 511;
        const float* wr = p.dWih0 + rr * DIN;
        const float* oc = p.outW + hc;
        float s = 0.0f;
        #pragma unroll
        for (int j = 0; j < DIN; j++) s = fmaf(__ldg(wr + j), __ldg(oc + j * H_), s);
        __stcg(&gM[o], s);
    }
    if (gt < G4) {
        const float* wr = p.dWih0 + gt * DIN;
        float s = 0.0f;
        #pragma unroll
        for (int j = 0; j < DIN; j++) s = fmaf(__ldg(wr + j), __ldg(p.outB + j), s);
        __stcg(&gB2[gt], s);
    }
    grid_bar(bgen);

    // ---- encoder ----
    // prologue: L0(0)   (reads h0(-1)=zeros in buf 1, writes h0(0) -> buf 0)
    lstm_phase(p.src, SLEN * DIN, p.eWih0, DIN,
               gH0[1], p.eWhh0,
               p.ebih0, p.ebhh0, nullptr, gC0, gH0[0], smem, smema);
    grid_bar(bgen);
    // merged main loop: phase t computes L1(t-1) and L0(t)
    for (int t = 1; t < SLEN; t++) {
        enc_merged(p, t, smem, smema);
        grid_bar(bgen);
    }
    // epilogue: L1(1023)  (h0(1023) in buf 1, h1(1022) in buf 0 -> h1(1023) buf 1)
    lstm_phase(gH0[1], H_, p.eWih1, H_,
               gH1[0], p.eWhh1,
               p.ebih1, p.ebhh1, nullptr, gC1, gH1[1], smem, smema);
    grid_bar(bgen);

    // ---- decoder: 512 steps x 2 phases (+ pred side job, all CTAs) ----
    // h_dec(t) in buf t&1; h_dec(-1) = encoder finals in buf 1.
    for (int t = 0; t < TLEN; t++) {
        const int rp = (t - 1) & 1, wp = t & 1;
        lstm_phase(t ? gH1[rp] : nullptr, H_, gM, t ? 512 : 0,
                   gH0[rp], p.dWhh0,
                   p.dbih0, p.dbhh0, t ? gB2 : nullptr, gC0, gH0[wp], smem, smema);
        if (t > 0) do_pred(p, gH1[rp], t - 1);
        grid_bar(bgen);
        lstm_phase(gH0[wp], H_, p.dWih1, H_,
                   gH1[rp], p.dWhh1,
                   p.dbih1, p.dbhh1, nullptr, gC1, gH1[wp], smem, smema);
        grid_bar(bgen);
    }
    // final pred for t = TLEN-1 (h1(511) in buf 1)
    do_pred(p, gH1[1], TLEN - 1);
}

extern "C" void kernel_launch(void* const* d_in, const int* in_sizes, int n_in,
                              void* d_out, int out_size)
{
    const int o = (in_sizes[1] < 100) ? 1 : 0;   // skip target_length scalar if present

    P p;
    p.src   = (const float*)d_in[0];
    p.eWih0 = (const float*)d_in[1 + o];
    p.eWhh0 = (const float*)d_in[2 + o];
    p.ebih0 = (const float*)d_in[3 + o];
    p.ebhh0 = (const float*)d_in[4 + o];
    p.eWih1 = (const float*)d_in[5 + o];
    p.eWhh1 = (const float*)d_in[6 + o];
    p.ebih1 = (const float*)d_in[7 + o];
    p.ebhh1 = (const float*)d_in[8 + o];
    p.dWih0 = (const float*)d_in[9 + o];
    p.dWhh0 = (const float*)d_in[10 + o];
    p.dbih0 = (const float*)d_in[11 + o];
    p.dbhh0 = (const float*)d_in[12 + o];
    p.dWih1 = (const float*)d_in[13 + o];
    p.dWhh1 = (const float*)d_in[14 + o];
    p.dbih1 = (const float*)d_in[15 + o];
    p.dbhh1 = (const float*)d_in[16 + o];
    p.outW  = (const float*)d_in[17 + o];
    p.outB  = (const float*)d_in[18 + o];
    p.out   = (float*)d_out;

    cudaFuncSetAttribute(seq2seq_kernel,
                         cudaFuncAttributeMaxDynamicSharedMemorySize, SMEM_BYTES);
    seq2seq_kernel<<<NB, NT, SMEM_BYTES>>>(p);
}

// round 15
// speedup vs baseline: 1.2746x; 1.1546x over previous
#include <cuda_runtime.h>
#include <cuda_bf16.h>
#include <cstdint>
#include <math.h>

// ---------------------------------------------------------------------------
// Seq2Seq LSTM (B=64, S=1024, T=512, H=512, D_IN=D_OUT=32), fp32.
// Persistent kernel: 128 CTAs x 512 threads, flag grid barrier (CTA0 agg).
// Each CTA owns 16 gate-rows (4 units x 4 gates) x 64 batches per layer-tile.
// Encoder phases merged (L1(t-1)+L0(t) in one barrier). Decoder unmerged.
// Staging: cp.async.cg, 4-slot warp-private ring (4-k chunks, depth-2),
// chunk loop fully unrolled via template NCH (all slot math compile-time).
// Finalize uses MUFU-based fast sigmoid/tanh (rel err ~1e-6).
// Decoder feedback GEMM folded into precomputed gM = dec_Wih0 @ out_W.
// ---------------------------------------------------------------------------

typedef unsigned int u32;

#define NB   128
#define NT   512
#define B_    64
#define H_    512
#define G4   2048
#define DIN   32
#define SLEN 1024
#define TLEN  512
#define CHUNK  4                      // k per staged chunk

#define WREG 1056                     // floats per warp region (16 rows x 66)
#define SMEM_FLOATS (16 * WREG)       // 16896 floats
#define SMEM_BYTES  (SMEM_FLOATS * 4) // 67584 B
// staging ring: 4 slots x 256 floats = 1024 <= WREG; reduction 16x66 = 1056.

struct P {
    const float *src;
    const float *eWih0, *eWhh0, *ebih0, *ebhh0;
    const float *eWih1, *eWhh1, *ebih1, *ebhh1;
    const float *dWih0, *dWhh0, *dbih0, *dbhh0;
    const float *dWih1, *dWhh1, *dbih1, *dbhh1;
    const float *outW, *outB;
    float *out;
};

// ---- persistent state (device globals; allocation-free scratch) ----
__device__ float gH0[2][B_ * H_];
__device__ float gH1[2][B_ * H_];
__device__ float gC0[B_ * H_];
__device__ float gC1[B_ * H_];
__device__ float gM[G4 * H_];      // dec_Wih0 @ out_W   [2048 x 512]
__device__ float gB2[G4];          // dec_Wih0 @ out_b
__device__ unsigned gFlag[NB];     // monotonic per-CTA arrival counters
__device__ volatile unsigned g_gen = 0;

// Proven barrier: CTA0's 128 threads poll the per-CTA flags; thread0
// publishes the new generation; other CTAs poll g_gen only.
__device__ __forceinline__ void grid_bar(unsigned &bgen) {
    __threadfence();
    __syncthreads();
    bgen++;
    if (blockIdx.x == 0) {
        if (threadIdx.x > 0 && threadIdx.x < NB) {
            volatile unsigned* f = gFlag + threadIdx.x;
            while (*f < bgen) __nanosleep(32);
        }
        __syncthreads();
        if (threadIdx.x == 0) { __threadfence(); g_gen = bgen; }
    } else {
        if (threadIdx.x == 0) {
            ((volatile unsigned*)gFlag)[blockIdx.x] = bgen;
            while (g_gen < bgen) __nanosleep(32);
        }
        __syncthreads();
    }
}

// Fast activations: MUFU-based, rel err ~1e-6 (threshold is 1e-3).
__device__ __forceinline__ float sigm(float x) {
    return __fdividef(1.0f, 1.0f + __expf(-x));
}
__device__ __forceinline__ float tanh_fast(float x) {
    // tanh(x) = 2*sigmoid(2x) - 1; saturates correctly for |x| large
    // (__expf overflow -> inf -> 0 -> -1; underflow -> 0 -> +1).
    return 2.0f * __fdividef(1.0f, 1.0f + __expf(-2.0f * x)) - 1.0f;
}

__device__ __forceinline__ float fma4(float4 a, float4 b, float s) {
    return fmaf(a.x, b.x, fmaf(a.y, b.y, fmaf(a.z, b.z, fmaf(a.w, b.w, s))));
}

// ---- cp.async helpers (L2-only .cg path: coherent with __stcg writes) ----
__device__ __forceinline__ void cpasync16(u32 saddr, const float* gptr) {
    asm volatile("cp.async.cg.shared.global [%0], [%1], 16;"
                 :: "r"(saddr), "l"(gptr) : "memory");
}
__device__ __forceinline__ void cpcommit() {
    asm volatile("cp.async.commit_group;" ::: "memory");
}
__device__ __forceinline__ void cpwait2() {
    asm volatile("cp.async.wait_group 2;" ::: "memory");
}

// GEMM term over a K-slice: NCH chunks of 4 k starting at kbase (NCH >= 2).
// acc[4 rows][8 batches]. W pre-offset to row 0, row stride WS.
// x: [64 rows, stride ld]. 4-slot smem ring (1024 B/slot), depth-2 pipeline,
// fully unrolled: slot offsets and k offsets are compile-time constants.
// Group discipline: preamble commits 2 groups; each iteration commits 1
// -> wait_group 2 at iter c guarantees chunk c landed (then syncwarp).
// Slot-reuse distance 4 > depth 3, so no overwrite hazard.
template<int WS, int NCH>
__device__ __forceinline__ void termK(
    const float* x, int ld, const float* __restrict__ W,
    int kbase, int lane, int bq, float acc[4][8],
    const float* buf, u32 bufa)
{
    const float* xr0 = x + (size_t)lane * ld + kbase;
    const float* xr1 = x + (size_t)(lane + 32) * ld + kbase;
    const u32 a0 = bufa + lane * 16;
    const u32 a1 = bufa + (lane + 32) * 16;

    // preamble: chunks 0 and 1 into slots 0 and 1
    #pragma unroll
    for (int c = 0; c < 2; c++) {
        const u32 s = (u32)(c * 1024);
        cpasync16(a0 + s, xr0 + c * CHUNK);
        cpasync16(a1 + s, xr1 + c * CHUNK);
        cpcommit();
    }

    #pragma unroll
    for (int c = 0; c < NCH; c++) {
        if (c + 2 < NCH) {
            const u32 s = (u32)(((c + 2) & 3) * 1024);
            cpasync16(a0 + s, xr0 + (c + 2) * CHUNK);
            cpasync16(a1 + s, xr1 + (c + 2) * CHUNK);
        }
        cpcommit();
        cpwait2();
        __syncwarp();                    // all lanes' chunk-c data visible
        const float* hb = buf + (c & 3) * 256 + bq * 4;
        const float* wb = W + kbase + c * CHUNK;
        float4 w0 = __ldg((const float4*)(wb + 0 * WS));
        float4 w1 = __ldg((const float4*)(wb + 1 * WS));
        float4 w2 = __ldg((const float4*)(wb + 2 * WS));
        float4 w3 = __ldg((const float4*)(wb + 3 * WS));
        #pragma unroll
        for (int m = 0; m < 8; m++) {
            float4 hv = *(const float4*)(hb + m * 32);   // rows m*8+bq, stride 4
            acc[0][m] = fma4(w0, hv, acc[0][m]);
            acc[1][m] = fma4(w1, hv, acc[1][m]);
            acc[2][m] = fma4(w2, hv, acc[2][m]);
            acc[3][m] = fma4(w3, hv, acc[3][m]);
        }
        __syncwarp();                    // slot c&3 free before reuse
    }
}

// K=32 single 4-k chunk (rows staged at stride 4 floats), slot 0.
// Issues 1 real + 2 pad commits, wait 2 -> real group done.
__device__ __forceinline__ void term32chunk(
    const float* x, int ld, const float* __restrict__ Wrow0,
    int kbase, int lane, int bq, float acc[4][8],
    const float* buf, u32 bufa)
{
    cpasync16(bufa + lane * 16,        x + (size_t)lane * ld + kbase);
    cpasync16(bufa + (lane + 32) * 16, x + (size_t)(lane + 32) * ld + kbase);
    cpcommit();
    cpcommit();
    cpcommit();
    cpwait2();
    __syncwarp();
    float4 w0 = __ldg((const float4*)(Wrow0 + 0 * DIN + kbase));
    float4 w1 = __ldg((const float4*)(Wrow0 + 1 * DIN + kbase));
    float4 w2 = __ldg((const float4*)(Wrow0 + 2 * DIN + kbase));
    float4 w3 = __ldg((const float4*)(Wrow0 + 3 * DIN + kbase));
    #pragma unroll
    for (int m = 0; m < 8; m++) {
        float4 hv = *(const float4*)(buf + ((m << 3) + bq) * 4);
        acc[0][m] = fma4(w0, hv, acc[0][m]);
        acc[1][m] = fma4(w1, hv, acc[1][m]);
        acc[2][m] = fma4(w2, hv, acc[2][m]);
        acc[3][m] = fma4(w3, hv, acc[3][m]);
    }
    __syncwarp();
}

// ---- unmerged LSTM phase (decoder + encoder prologue/epilogue) ----
// 16 warps, 32-k slice each per term (8 chunks). KA in {0, 32, 512}.
__device__ __forceinline__ void lstm_phase(
    const float* xA, int ldA, const float* __restrict__ WA, int KA,
    const float* xB, const float* __restrict__ WB,
    const float* __restrict__ bih, const float* __restrict__ bhh,
    const float* __restrict__ b2,
    float* __restrict__ cst, float* __restrict__ hout,
    float* smem, u32 smema)
{
    const int tid  = threadIdx.x;
    const int w    = tid >> 5, lane = tid & 31;
    const int gate = lane >> 3, bq = lane & 7;
    float* buf = smem + w * WREG;
    const u32 bufa = smema + (u32)(w * WREG * 4);

    float acc[4][8];
    #pragma unroll
    for (int r = 0; r < 4; r++)
        #pragma unroll
        for (int m = 0; m < 8; m++) acc[r][m] = 0.0f;

    const size_t rowbase = (size_t)((gate << 9) + (blockIdx.x << 2));
    if (KA == 512)
        termK<512, 8>(xA, ldA, WA + rowbase * H_, w * 32, lane, bq, acc, buf, bufa);
    else if (KA == 32 && w < 8)
        term32chunk(xA, ldA, WA + rowbase * DIN, w * 4, lane, bq, acc, buf, bufa);
    termK<512, 8>(xB, H_, WB + rowbase * H_, w * 32, lane, bq, acc, buf, bufa);

    // partial store into the warp's OWN region (overwrites its staging):
    // offset = row*66 + b  (bank = gate*8 + bq -> conflict-free)
    #pragma unroll
    for (int rr = 0; rr < 4; rr++)
        #pragma unroll
        for (int m = 0; m < 8; m++)
            buf[((gate << 2) + rr) * 66 + (m << 3) + bq] = acc[rr][m];
    __syncthreads();

    if (tid < 256) {
        const int u = tid & 3, b = tid >> 2;
        const int ug = (blockIdx.x << 2) + u;
        float g4v[4];
        #pragma unroll
        for (int g = 0; g < 4; g++) {
            float s = 0.0f;
            #pragma unroll
            for (int s16 = 0; s16 < 16; s16++)
                s += smem[s16 * WREG + ((g << 2) + u) * 66 + b];
            int r = (g << 9) + ug;
            s += __ldg(bih + r) + __ldg(bhh + r);
            if (b2) s += __ldg(b2 + r);
            g4v[g] = s;
        }
        const int idx = (b << 9) + ug;
        float cp = __ldcg(cst + idx);
        float cn = sigm(g4v[1]) * cp + sigm(g4v[0]) * tanh_fast(g4v[2]);
        __stcg(cst + idx, cn);
        __stcg(hout + idx, sigm(g4v[3]) * tanh_fast(cn));
    }
}

// ---- merged encoder phase t (1..1023): computes L1(t-1) AND L0(t) ----
// Warps 0-7: L0 tile (src(t)@eWih0 + h0(t-1)@eWhh0), 64-k slices (16 chunks).
// Warps 8-15: L1 tile (h0(t-1)@eWih1 + h1(t-2)@eWhh1), 64-k slices.
__device__ __forceinline__ void enc_merged(const P& p, int t,
                                           float* smem, u32 smema)
{
    const int tid  = threadIdx.x;
    const int w    = tid >> 5, lane = tid & 31;
    const int grp  = w >> 3, seg = w & 7;
    const int gate = lane >> 3, bq = lane & 7;
    float* buf = smem + w * WREG;
    const u32 bufa = smema + (u32)(w * WREG * 4);

    float acc[4][8];
    #pragma unroll
    for (int r = 0; r < 4; r++)
        #pragma unroll
        for (int m = 0; m < 8; m++) acc[r][m] = 0.0f;

    const size_t rowbase = (size_t)((gate << 9) + (blockIdx.x << 2));
    const float* h0prev = gH0[(t - 1) & 1];     // h0(t-1)
    if (grp == 0) {
        term32chunk(p.src + t * DIN, SLEN * DIN, p.eWih0 + rowbase * DIN,
                    seg * 4, lane, bq, acc, buf, bufa);
        termK<512, 16>(h0prev, H_, p.eWhh0 + rowbase * H_,
                       seg * 64, lane, bq, acc, buf, bufa);
    } else {
        const float* h1prev2 = gH1[t & 1];      // h1(t-2) lives in buf t&1
        termK<512, 16>(h0prev,  H_, p.eWih1 + rowbase * H_,
                       seg * 64, lane, bq, acc, buf, bufa);
        termK<512, 16>(h1prev2, H_, p.eWhh1 + rowbase * H_,
                       seg * 64, lane, bq, acc, buf, bufa);
    }

    // partial store into the warp's OWN region (row within its layer tile)
    #pragma unroll
    for (int rr = 0; rr < 4; rr++)
        #pragma unroll
        for (int m = 0; m < 8; m++)
            buf[((gate << 2) + rr) * 66 + (m << 3) + bq] = acc[rr][m];
    __syncthreads();

    // finalize: 512 threads, one (layer, b, u) each; sum the 8 warps of
    // the thread's layer group.
    {
        const int L = tid >> 8, rem = tid & 255;
        const int u = rem & 3, b = rem >> 2;
        const int ug = (blockIdx.x << 2) + u;
        const float* bih = L ? p.ebih1 : p.ebih0;
        const float* bhh = L ? p.ebhh1 : p.ebhh0;
        float g4v[4];
        #pragma unroll
        for (int g = 0; g < 4; g++) {
            float s = 0.0f;
            #pragma unroll
            for (int s8 = 0; s8 < 8; s8++)
                s += smem[((L << 3) + s8) * WREG + ((g << 2) + u) * 66 + b];
            int r = (g << 9) + ug;
            s += __ldg(bih + r) + __ldg(bhh + r);
            g4v[g] = s;
        }
        float* cst  = L ? gC1 : gC0;
        float* hout = L ? gH1[(t - 1) & 1] : gH0[t & 1];
        const int idx = (b << 9) + ug;
        float cp = __ldcg(cst + idx);
        float cn = sigm(g4v[1]) * cp + sigm(g4v[0]) * tanh_fast(g4v[2]);
        __stcg(cst + idx, cn);
        __stcg(hout + idx, sigm(g4v[3]) * tanh_fast(cn));
    }
}

// pred(t) = h1 @ out_W.T + out_b -> d_out[:, t, :].
// Spread over ALL CTAs: 64 threads/CTA, 16 outputs/CTA.
__device__ __forceinline__ void do_pred(const P& p, const float* __restrict__ h1, int t)
{
    if (threadIdx.x >= 64) return;
    int g = (blockIdx.x << 6) + threadIdx.x;   // 0..8191
    int oid = g >> 2, part = g & 3;            // 2048 outputs, K split by 4
    int b = oid >> 5, j = oid & 31;
    const float* hr = h1 + (b << 9) + (part << 7);
    const float* wr = p.outW + (j << 9) + (part << 7);
    float s = 0.0f;
    #pragma unroll
    for (int k = 0; k < 128; k += 4) {
        float4 hv = __ldcg((const float4*)(hr + k));
        float4 wv = __ldg ((const float4*)(wr + k));
        s = fmaf(hv.x, wv.x, fmaf(hv.y, wv.y, fmaf(hv.z, wv.z, fmaf(hv.w, wv.w, s))));
    }
    s += __shfl_xor_sync(0xffffffffu, s, 1);
    s += __shfl_xor_sync(0xffffffffu, s, 2);
    if (part == 0)
        p.out[((long)b << 14) + (t << 5) + j] = s + __ldg(p.outB + j);
}

__global__ void __launch_bounds__(NT, 1) seq2seq_kernel(P p)
{
    extern __shared__ float smem[];
    const u32 smema = (u32)__cvta_generic_to_shared(smem);
    const int gt = blockIdx.x * NT + threadIdx.x;   // 0..65535
    unsigned bgen = g_gen;                          // monotonic barrier epoch

    // ---- zero init: h(-1) lives in buffer 1 ----
    if (gt < B_ * H_) {
        __stcg(&gH0[1][gt], 0.0f);
        __stcg(&gH1[1][gt], 0.0f);
        __stcg(&gC0[gt],    0.0f);
        __stcg(&gC1[gt],    0.0f);
    }
    grid_bar(bgen);

    // ---- precompute M = dec_Wih0 @ out_W, b2 = dec_Wih0 @ out_b ----
    for (int o = gt; o < G4 * H_; o += NB * NT) {
        int rr = o >> 9, hc = o & 511;
        const float* wr = p.dWih0 + rr * DIN;
        const float* oc = p.outW + hc;
        float s = 0.0f;
        #pragma unroll
        for (int j = 0; j < DIN; j++) s = fmaf(__ldg(wr + j), __ldg(oc + j * H_), s);
        __stcg(&gM[o], s);
    }
    if (gt < G4) {
        const float* wr = p.dWih0 + gt * DIN;
        float s = 0.0f;
        #pragma unroll
        for (int j = 0; j < DIN; j++) s = fmaf(__ldg(wr + j), __ldg(p.outB + j), s);
        __stcg(&gB2[gt], s);
    }
    grid_bar(bgen);

    // ---- encoder ----
    // prologue: L0(0)   (reads h0(-1)=zeros in buf 1, writes h0(0) -> buf 0)
    lstm_phase(p.src, SLEN * DIN, p.eWih0, DIN,
               gH0[1], p.eWhh0,
               p.ebih0, p.ebhh0, nullptr, gC0, gH0[0], smem, smema);
    grid_bar(bgen);
    // merged main loop: phase t computes L1(t-1) and L0(t)
    for (int t = 1; t < SLEN; t++) {
        enc_merged(p, t, smem, smema);
        grid_bar(bgen);
    }
    // epilogue: L1(1023)  (h0(1023) in buf 1, h1(1022) in buf 0 -> h1(1023) buf 1)
    lstm_phase(gH0[1], H_, p.eWih1, H_,
               gH1[0], p.eWhh1,
               p.ebih1, p.ebhh1, nullptr, gC1, gH1[1], smem, smema);
    grid_bar(bgen);

    // ---- decoder: 512 steps x 2 phases (+ pred side job, all CTAs) ----
    // h_dec(t) in buf t&1; h_dec(-1) = encoder finals in buf 1.
    for (int t = 0; t < TLEN; t++) {
        const int rp = (t - 1) & 1, wp = t & 1;
        lstm_phase(t ? gH1[rp] : nullptr, H_, gM, t ? 512 : 0,
                   gH0[rp], p.dWhh0,
                   p.dbih0, p.dbhh0, t ? gB2 : nullptr, gC0, gH0[wp], smem, smema);
        if (t > 0) do_pred(p, gH1[rp], t - 1);
        grid_bar(bgen);
        lstm_phase(gH0[wp], H_, p.dWih1, H_,
                   gH1[rp], p.dWhh1,
                   p.dbih1, p.dbhh1, nullptr, gC1, gH1[wp], smem, smema);
        grid_bar(bgen);
    }
    // final pred for t = TLEN-1 (h1(511) in buf 1)
    do_pred(p, gH1[1], TLEN - 1);
}

extern "C" void kernel_launch(void* const* d_in, const int* in_sizes, int n_in,
                              void* d_out, int out_size)
{
    const int o = (in_sizes[1] < 100) ? 1 : 0;   // skip target_length scalar if present

    P p;
    p.src   = (const float*)d_in[0];
    p.eWih0 = (const float*)d_in[1 + o];
    p.eWhh0 = (const float*)d_in[2 + o];
    p.ebih0 = (const float*)d_in[3 + o];
    p.ebhh0 = (const float*)d_in[4 + o];
    p.eWih1 = (const float*)d_in[5 + o];
    p.eWhh1 = (const float*)d_in[6 + o];
    p.ebih1 = (const float*)d_in[7 + o];
    p.ebhh1 = (const float*)d_in[8 + o];
    p.dWih0 = (const float*)d_in[9 + o];
    p.dWhh0 = (const float*)d_in[10 + o];
    p.dbih0 = (const float*)d_in[11 + o];
    p.dbhh0 = (const float*)d_in[12 + o];
    p.dWih1 = (const float*)d_in[13 + o];
    p.dWhh1 = (const float*)d_in[14 + o];
    p.dbih1 = (const float*)d_in[15 + o];
    p.dbhh1 = (const float*)d_in[16 + o];
    p.outW  = (const float*)d_in[17 + o];
    p.outB  = (const float*)d_in[18 + o];
    p.out   = (float*)d_out;

    cudaFuncSetAttribute(seq2seq_kernel,
                         cudaFuncAttributeMaxDynamicSharedMemorySize, SMEM_BYTES);
    seq2seq_kernel<<<NB, NT, SMEM_BYTES>>>(p);
}